// round 1
// baseline (speedup 1.0000x reference)
#include <cuda_runtime.h>

#define BB 256
#define NTOK 63
#define DD 128
#define EE 8
#define HH 256
#define T2 160
#define PITCH 68

__device__ float g_gates[BB * 2];
__device__ int   g_eidx[BB * 2];

// ---------------- Router: mean-pool tokens 1..63, logits, softmax, top-2 ----------------
__global__ void router_kernel(const float* __restrict__ x,
                              const float* __restrict__ rw,
                              const float* __restrict__ rb) {
    int b = blockIdx.x;
    __shared__ float pooled[DD];
    __shared__ float logits[EE];
    int d = threadIdx.x;  // 128 threads
    const float* xb = x + b * 64 * DD;
    float s = 0.f;
    #pragma unroll 4
    for (int n = 1; n < 64; n++) s += xb[n * DD + d];
    pooled[d] = s * (1.0f / 63.0f);
    __syncthreads();
    if (d < EE) {
        float l = rb[d];
        #pragma unroll 4
        for (int dd = 0; dd < DD; dd++) l += pooled[dd] * rw[dd * EE + d];
        logits[d] = l;
    }
    __syncthreads();
    if (d == 0) {
        float mx = logits[0];
        #pragma unroll
        for (int e = 1; e < EE; e++) mx = fmaxf(mx, logits[e]);
        float p[EE];
        float se = 0.f;
        #pragma unroll
        for (int e = 0; e < EE; e++) { p[e] = expf(logits[e] - mx); se += p[e]; }
        int i1 = 0;
        #pragma unroll
        for (int e = 1; e < EE; e++) if (p[e] > p[i1]) i1 = e;
        int i2 = (i1 == 0) ? 1 : 0;
        #pragma unroll
        for (int e = 0; e < EE; e++) if (e != i1 && p[e] > p[i2]) i2 = e;
        float inv = 1.f / se;
        g_eidx[b * 2 + 0]  = i1;
        g_gates[b * 2 + 0] = p[i1] * inv;
        g_eidx[b * 2 + 1]  = i2;
        g_gates[b * 2 + 1] = p[i2] * inv;
    }
}

// ---------------- packed f32x2 helpers (double-rate fp32 on sm_103a) ----------------
__device__ __forceinline__ unsigned long long pack2(float lo, float hi) {
    unsigned long long r;
    asm("mov.b64 %0, {%1, %2};" : "=l"(r) : "f"(lo), "f"(hi));
    return r;
}
__device__ __forceinline__ void unpack2(unsigned long long v, float& lo, float& hi) {
    asm("mov.b64 {%0, %1}, %2;" : "=f"(lo), "=f"(hi) : "l"(v));
}
__device__ __forceinline__ void ffma2(unsigned long long& d,
                                      unsigned long long a,
                                      unsigned long long b) {
    asm("fma.rn.f32x2 %0, %1, %2, %3;" : "=l"(d) : "l"(a), "l"(b), "l"(d));
}

// ---------------- Fused 2-expert FFN per batch ----------------
// One CTA per batch. xa and h staged in smem TRANSPOSED: [dim][token], pitch 68.
// Warp layout: all 32 lanes share a row-tile (rows n0..n0+7) -> smem loads broadcast.
// GEMM1: each thread owns 8 cols (colg + 32c), GEMM2: 5 cols. fp32x2 packed FMA.
__global__ __launch_bounds__(256, 2) void moe_kernel(
    const float* __restrict__ x,
    const float* __restrict__ w1, const float* __restrict__ b1,
    const float* __restrict__ w2, const float* __restrict__ b2,
    float* __restrict__ out) {
    extern __shared__ float smem[];
    float* xs = smem;               // [DD][PITCH]  value(row n, dim d) at xs[d*PITCH+n]
    float* hs = smem + DD * PITCH;  // [HH][PITCH]  value(row n, hid j) at hs[j*PITCH+n]

    int b = blockIdx.x;
    int tid = threadIdx.x;

    // Load xa = x[b, 1:64, :] transposed into smem; pad row 63 with zeros.
    const float* xb = x + b * 64 * DD + DD;
    for (int idx = tid; idx < 64 * DD; idx += 256) {
        int n = idx >> 7, d = idx & 127;
        xs[d * PITCH + n] = (n < NTOK) ? xb[n * DD + d] : 0.f;
    }
    __syncthreads();

    const int n0   = (tid >> 5) * 8;  // row tile (same for whole warp)
    const int colg = tid & 31;        // lane -> column group
    float* ob = out + b * NTOK * T2;

    for (int kk = 0; kk < 2; kk++) {
        const int   e = g_eidx[b * 2 + kk];
        const float g = g_gates[b * 2 + kk];

        // ---- GEMM1: h[n][j] = relu(sum_d xa[n][d] * w1[e][d][j] + b1[e][j]) ----
        {
            unsigned long long acc[4][8];
            #pragma unroll
            for (int i = 0; i < 4; i++)
                #pragma unroll
                for (int c = 0; c < 8; c++) acc[i][c] = 0ull;

            const float* w1e = w1 + e * DD * HH + colg;
            #pragma unroll 2
            for (int d = 0; d < DD; d++) {
                const ulonglong2* ap = (const ulonglong2*)(xs + d * PITCH + n0);
                ulonglong2 a01 = ap[0];
                ulonglong2 a23 = ap[1];
                unsigned long long av[4] = {a01.x, a01.y, a23.x, a23.y};
                const float* wr = w1e + d * HH;
                #pragma unroll
                for (int c = 0; c < 8; c++) {
                    float w = wr[32 * c];
                    unsigned long long wp = pack2(w, w);
                    #pragma unroll
                    for (int i = 0; i < 4; i++) ffma2(acc[i][c], av[i], wp);
                }
            }
            #pragma unroll
            for (int c = 0; c < 8; c++) {
                int j = colg + 32 * c;
                float bv = b1[e * HH + j];
                float* hr = hs + j * PITCH + n0;
                #pragma unroll
                for (int i = 0; i < 4; i++) {
                    float lo, hi;
                    unpack2(acc[i][c], lo, hi);
                    hr[2 * i]     = fmaxf(lo + bv, 0.f);
                    hr[2 * i + 1] = fmaxf(hi + bv, 0.f);
                }
            }
        }
        __syncthreads();

        // ---- GEMM2: o[n][j] = sum_h h[n][hd] * w2[e][hd][j] + b2[e][j] ----
        {
            unsigned long long acc2[4][5];
            #pragma unroll
            for (int i = 0; i < 4; i++)
                #pragma unroll
                for (int c = 0; c < 5; c++) acc2[i][c] = 0ull;

            const float* w2e = w2 + e * HH * T2 + colg;
            #pragma unroll 2
            for (int hd = 0; hd < HH; hd++) {
                const ulonglong2* hp = (const ulonglong2*)(hs + hd * PITCH + n0);
                ulonglong2 h01 = hp[0];
                ulonglong2 h23 = hp[1];
                unsigned long long hv[4] = {h01.x, h01.y, h23.x, h23.y};
                const float* wr = w2e + hd * T2;
                #pragma unroll
                for (int c = 0; c < 5; c++) {
                    float w = wr[32 * c];
                    unsigned long long wp = pack2(w, w);
                    #pragma unroll
                    for (int i = 0; i < 4; i++) ffma2(acc2[i][c], hv[i], wp);
                }
            }
            #pragma unroll
            for (int c = 0; c < 5; c++) {
                int j = colg + 32 * c;
                float bv = b2[e * T2 + j];
                #pragma unroll
                for (int i = 0; i < 4; i++) {
                    float lo, hi;
                    unpack2(acc2[i][c], lo, hi);
                    int n = n0 + 2 * i;
                    float vlo = g * (lo + bv);
                    float vhi = g * (hi + bv);
                    if (kk == 0) {
                        ob[n * T2 + j] = vlo;
                        if (n + 1 < NTOK) ob[(n + 1) * T2 + j] = vhi;
                    } else {
                        ob[n * T2 + j] += vlo;
                        if (n + 1 < NTOK) ob[(n + 1) * T2 + j] += vhi;
                    }
                }
            }
        }
        __syncthreads();
    }
}

extern "C" void kernel_launch(void* const* d_in, const int* in_sizes, int n_in,
                              void* d_out, int out_size) {
    const float* x  = (const float*)d_in[0];
    const float* rw = (const float*)d_in[1];
    const float* rb = (const float*)d_in[2];
    const float* w1 = (const float*)d_in[3];
    const float* b1 = (const float*)d_in[4];
    const float* w2 = (const float*)d_in[5];
    const float* b2 = (const float*)d_in[6];
    float* out = (float*)d_out;

    router_kernel<<<BB, 128>>>(x, rw, rb);

    const int smem_bytes = (DD + HH) * PITCH * (int)sizeof(float);
    cudaFuncSetAttribute(moe_kernel, cudaFuncAttributeMaxDynamicSharedMemorySize,
                         smem_bytes);
    moe_kernel<<<BB, 256, smem_bytes>>>(x, w1, b1, w2, b2, out);
}

// round 2
// speedup vs baseline: 1.1829x; 1.1829x over previous
#include <cuda_runtime.h>

#define BB 256
#define NTOK 63
#define DD 128
#define EE 8
#define HH 256
#define T2 160
#define PITCH 68

__device__ float g_gates[BB * 2];
__device__ int   g_eidx[BB * 2];

// ---------------- Router ----------------
__global__ void router_kernel(const float* __restrict__ x,
                              const float* __restrict__ rw,
                              const float* __restrict__ rb) {
    int b = blockIdx.x;
    __shared__ float pooled[DD];
    __shared__ float logits[EE];
    int d = threadIdx.x;  // 128 threads
    const float* xb = x + b * 64 * DD;
    float s = 0.f;
    #pragma unroll 4
    for (int n = 1; n < 64; n++) s += xb[n * DD + d];
    pooled[d] = s * (1.0f / 63.0f);
    __syncthreads();
    if (d < EE) {
        float l = rb[d];
        #pragma unroll 4
        for (int dd = 0; dd < DD; dd++) l += pooled[dd] * rw[dd * EE + d];
        logits[d] = l;
    }
    __syncthreads();
    if (d == 0) {
        float mx = logits[0];
        #pragma unroll
        for (int e = 1; e < EE; e++) mx = fmaxf(mx, logits[e]);
        float p[EE];
        float se = 0.f;
        #pragma unroll
        for (int e = 0; e < EE; e++) { p[e] = expf(logits[e] - mx); se += p[e]; }
        int i1 = 0;
        #pragma unroll
        for (int e = 1; e < EE; e++) if (p[e] > p[i1]) i1 = e;
        int i2 = (i1 == 0) ? 1 : 0;
        #pragma unroll
        for (int e = 0; e < EE; e++) if (e != i1 && p[e] > p[i2]) i2 = e;
        float inv = 1.f / se;
        g_eidx[b * 2 + 0]  = i1;
        g_gates[b * 2 + 0] = p[i1] * inv;
        g_eidx[b * 2 + 1]  = i2;
        g_gates[b * 2 + 1] = p[i2] * inv;
    }
}

// ---------------- packed f32x2 helpers ----------------
__device__ __forceinline__ unsigned long long pack2(float lo, float hi) {
    unsigned long long r;
    asm("mov.b64 %0, {%1, %2};" : "=l"(r) : "f"(lo), "f"(hi));
    return r;
}
__device__ __forceinline__ void unpack2(unsigned long long v, float& lo, float& hi) {
    asm("mov.b64 {%0, %1}, %2;" : "=f"(lo), "=f"(hi) : "l"(v));
}
__device__ __forceinline__ void ffma2(unsigned long long& d,
                                      unsigned long long a,
                                      unsigned long long b) {
    asm("fma.rn.f32x2 %0, %1, %2, %3;" : "=l"(d) : "l"(a), "l"(b), "l"(d));
}

// ---------------- Fused 2-expert FFN per batch ----------------
// One CTA per batch, 256 threads. Each warp owns 8 token rows (n0..n0+7);
// lanes own columns. GEMM1 cols: {4*colg..+3} U {128+4*colg..+3} (2x LDG.128/d).
// GEMM2 cols: {4*colg..+3} U {128+colg}  (LDG.128 + LDG.32 per hd).
// Weights software-pipelined (prefetch distance 1). No block barriers after
// the xs load: each warp's GEMM2 reads only hs data its own lanes wrote.
__global__ __launch_bounds__(256, 2) void moe_kernel(
    const float* __restrict__ x,
    const float* __restrict__ w1, const float* __restrict__ b1,
    const float* __restrict__ w2, const float* __restrict__ b2,
    float* __restrict__ out) {
    extern __shared__ float smem[];
    float* xs = smem;               // [DD][PITCH]
    float* hs = smem + DD * PITCH;  // [HH][PITCH]

    int b = blockIdx.x;
    int tid = threadIdx.x;

    const float* xb = x + b * 64 * DD + DD;
    for (int idx = tid; idx < 64 * DD; idx += 256) {
        int n = idx >> 7, d = idx & 127;
        xs[d * PITCH + n] = (n < NTOK) ? xb[n * DD + d] : 0.f;
    }
    __syncthreads();

    const int n0   = (tid >> 5) * 8;
    const int colg = tid & 31;
    const int c4   = colg * 4;
    float* ob = out + b * NTOK * T2;

    #pragma unroll
    for (int kk = 0; kk < 2; kk++) {
        const int   e = g_eidx[b * 2 + kk];
        const float g = g_gates[b * 2 + kk];

        // ---- GEMM1: h = relu(xa @ W1e + b1e), staged transposed in hs ----
        {
            unsigned long long acc[4][8];
            #pragma unroll
            for (int i = 0; i < 4; i++)
                #pragma unroll
                for (int c = 0; c < 8; c++) acc[i][c] = 0ull;

            const float* w1e = w1 + e * DD * HH;
            const float4* wg0 = (const float4*)(w1e + c4);
            const float4* wg1 = (const float4*)(w1e + 128 + c4);

            float4 wa = wg0[0];
            float4 wb = wg1[0];
            #pragma unroll 2
            for (int d = 0; d < DD - 1; d++) {
                float4 nwa = wg0[(d + 1) * (HH / 4)];
                float4 nwb = wg1[(d + 1) * (HH / 4)];
                const ulonglong2* ap = (const ulonglong2*)(xs + d * PITCH + n0);
                ulonglong2 a01 = ap[0];
                ulonglong2 a23 = ap[1];
                unsigned long long av[4] = {a01.x, a01.y, a23.x, a23.y};
                float wv[8] = {wa.x, wa.y, wa.z, wa.w, wb.x, wb.y, wb.z, wb.w};
                #pragma unroll
                for (int c = 0; c < 8; c++) {
                    unsigned long long wp = pack2(wv[c], wv[c]);
                    #pragma unroll
                    for (int i = 0; i < 4; i++) ffma2(acc[i][c], av[i], wp);
                }
                wa = nwa; wb = nwb;
            }
            {   // last d
                const int d = DD - 1;
                const ulonglong2* ap = (const ulonglong2*)(xs + d * PITCH + n0);
                ulonglong2 a01 = ap[0];
                ulonglong2 a23 = ap[1];
                unsigned long long av[4] = {a01.x, a01.y, a23.x, a23.y};
                float wv[8] = {wa.x, wa.y, wa.z, wa.w, wb.x, wb.y, wb.z, wb.w};
                #pragma unroll
                for (int c = 0; c < 8; c++) {
                    unsigned long long wp = pack2(wv[c], wv[c]);
                    #pragma unroll
                    for (int i = 0; i < 4; i++) ffma2(acc[i][c], av[i], wp);
                }
            }
            #pragma unroll
            for (int c = 0; c < 8; c++) {
                int j = (c < 4) ? (c4 + c) : (128 + c4 + (c - 4));
                float bv = b1[e * HH + j];
                float* hr = hs + j * PITCH + n0;
                #pragma unroll
                for (int i = 0; i < 4; i++) {
                    float lo, hi;
                    unpack2(acc[i][c], lo, hi);
                    hr[2 * i]     = fmaxf(lo + bv, 0.f);
                    hr[2 * i + 1] = fmaxf(hi + bv, 0.f);
                }
            }
        }
        __syncwarp();

        // ---- GEMM2: o = h @ W2e + b2e, gated accumulate into out ----
        {
            unsigned long long acc2[4][5];
            #pragma unroll
            for (int i = 0; i < 4; i++)
                #pragma unroll
                for (int c = 0; c < 5; c++) acc2[i][c] = 0ull;

            const float* w2e = w2 + e * HH * T2;
            const float4* vg0 = (const float4*)(w2e + c4);
            const float*  vg1 = w2e + 128 + colg;

            float4 va = vg0[0];
            float  vs = vg1[0];
            #pragma unroll 2
            for (int hd = 0; hd < HH - 1; hd++) {
                float4 nva = vg0[(hd + 1) * (T2 / 4)];
                float  nvs = vg1[(hd + 1) * T2];
                const ulonglong2* hp = (const ulonglong2*)(hs + hd * PITCH + n0);
                ulonglong2 h01 = hp[0];
                ulonglong2 h23 = hp[1];
                unsigned long long hv[4] = {h01.x, h01.y, h23.x, h23.y};
                float wv[5] = {va.x, va.y, va.z, va.w, vs};
                #pragma unroll
                for (int c = 0; c < 5; c++) {
                    unsigned long long wp = pack2(wv[c], wv[c]);
                    #pragma unroll
                    for (int i = 0; i < 4; i++) ffma2(acc2[i][c], hv[i], wp);
                }
                va = nva; vs = nvs;
            }
            {   // last hd
                const int hd = HH - 1;
                const ulonglong2* hp = (const ulonglong2*)(hs + hd * PITCH + n0);
                ulonglong2 h01 = hp[0];
                ulonglong2 h23 = hp[1];
                unsigned long long hv[4] = {h01.x, h01.y, h23.x, h23.y};
                float wv[5] = {va.x, va.y, va.z, va.w, vs};
                #pragma unroll
                for (int c = 0; c < 5; c++) {
                    unsigned long long wp = pack2(wv[c], wv[c]);
                    #pragma unroll
                    for (int i = 0; i < 4; i++) ffma2(acc2[i][c], hv[i], wp);
                }
            }

            float bv4[4];
            #pragma unroll
            for (int c = 0; c < 4; c++) bv4[c] = b2[e * T2 + c4 + c];
            float bvs = b2[e * T2 + 128 + colg];

            #pragma unroll
            for (int i = 0; i < 4; i++) {
                float lo[5], hi[5];
                #pragma unroll
                for (int c = 0; c < 5; c++) unpack2(acc2[i][c], lo[c], hi[c]);
                int n = n0 + 2 * i;
                float4 v0 = make_float4(g * (lo[0] + bv4[0]), g * (lo[1] + bv4[1]),
                                        g * (lo[2] + bv4[2]), g * (lo[3] + bv4[3]));
                float s0 = g * (lo[4] + bvs);
                float4 v1 = make_float4(g * (hi[0] + bv4[0]), g * (hi[1] + bv4[1]),
                                        g * (hi[2] + bv4[2]), g * (hi[3] + bv4[3]));
                float s1 = g * (hi[4] + bvs);
                float* r0 = ob + n * T2;
                if (kk == 0) {
                    *(float4*)(r0 + c4) = v0;
                    r0[128 + colg] = s0;
                    if (n + 1 < NTOK) {
                        float* r1 = r0 + T2;
                        *(float4*)(r1 + c4) = v1;
                        r1[128 + colg] = s1;
                    }
                } else {
                    float4 t = *(const float4*)(r0 + c4);
                    t.x += v0.x; t.y += v0.y; t.z += v0.z; t.w += v0.w;
                    *(float4*)(r0 + c4) = t;
                    r0[128 + colg] += s0;
                    if (n + 1 < NTOK) {
                        float* r1 = r0 + T2;
                        float4 u = *(const float4*)(r1 + c4);
                        u.x += v1.x; u.y += v1.y; u.z += v1.z; u.w += v1.w;
                        *(float4*)(r1 + c4) = u;
                        r1[128 + colg] += s1;
                    }
                }
            }
        }
        __syncwarp();
    }
}

extern "C" void kernel_launch(void* const* d_in, const int* in_sizes, int n_in,
                              void* d_out, int out_size) {
    const float* x  = (const float*)d_in[0];
    const float* rw = (const float*)d_in[1];
    const float* rb = (const float*)d_in[2];
    const float* w1 = (const float*)d_in[3];
    const float* b1 = (const float*)d_in[4];
    const float* w2 = (const float*)d_in[5];
    const float* b2 = (const float*)d_in[6];
    float* out = (float*)d_out;

    router_kernel<<<BB, 128>>>(x, rw, rb);

    const int smem_bytes = (DD + HH) * PITCH * (int)sizeof(float);
    cudaFuncSetAttribute(moe_kernel, cudaFuncAttributeMaxDynamicSharedMemorySize,
                         smem_bytes);
    moe_kernel<<<BB, 256, smem_bytes>>>(x, w1, b1, w2, b2, out);
}